// round 4
// baseline (speedup 1.0000x reference)
#include <cuda_runtime.h>
#include <math.h>

#define B_  16
#define C_  256
#define N_  1024
#define G_  4
#define CG  64          // channels per group

// packed fp32x2 helpers (sm_103a; ptxas never emits these from C++)
#define FMA_F32X2(d, a, b, c) \
    asm("fma.rn.f32x2 %0, %1, %2, %3;" : "=l"(d) : "l"(a), "l"(b), "l"(c))
#define UNPACK_F32X2(lo, hi, in) \
    asm("mov.b64 {%0, %1}, %2;" : "=f"(lo), "=f"(hi) : "l"(in))

// ---------------- scratch (static device memory; no allocs) ----------------
__device__ float g_h[B_ * N_ * C_];        // normalized activations [B,N,C], later reused for attn output
__device__ float g_q[B_ * N_ * C_];
__device__ float g_k[B_ * N_ * C_];
__device__ float g_v[B_ * N_ * C_];
__device__ float g_s[B_ * N_ * N_];        // scores / attn [B,N,N]  (67 MB)
__device__ float g_mean[B_ * G_];
__device__ float g_rstd[B_ * G_];

// ---------------- GroupNorm stats: one block per (b,g) ----------------
__global__ void gn_stats(const float* __restrict__ x) {
    int bg = blockIdx.x;                           // 0..63
    const float4* xp4 = (const float4*)(x + (size_t)bg * (CG * N_));
    float s = 0.f, ss = 0.f;
    const int n4 = (CG * N_) / 4;                  // 16384 float4
    for (int i = threadIdx.x; i < n4; i += blockDim.x) {
        float4 v = xp4[i];
        s  += v.x + v.y + v.z + v.w;
        ss += v.x * v.x + v.y * v.y + v.z * v.z + v.w * v.w;
    }
    __shared__ float rs[16], rss[16];
    #pragma unroll
    for (int o = 16; o; o >>= 1) {
        s  += __shfl_down_sync(0xffffffffu, s, o);
        ss += __shfl_down_sync(0xffffffffu, ss, o);
    }
    int w = threadIdx.x >> 5, l = threadIdx.x & 31;
    if (l == 0) { rs[w] = s; rss[w] = ss; }
    __syncthreads();
    if (w == 0) {
        int nw = blockDim.x >> 5;
        s  = (l < nw) ? rs[l]  : 0.f;
        ss = (l < nw) ? rss[l] : 0.f;
        #pragma unroll
        for (int o = 16; o; o >>= 1) {
            s  += __shfl_down_sync(0xffffffffu, s, o);
            ss += __shfl_down_sync(0xffffffffu, ss, o);
        }
        if (l == 0) {
            const float inv_n = 1.0f / (CG * N_);
            float m   = s * inv_n;
            float var = ss * inv_n - m * m;
            g_mean[bg] = m;
            g_rstd[bg] = rsqrtf(var + 1e-5f);
        }
    }
}

// ---------------- normalize + transpose [B,C,N] -> h[B,N,C] ----------------
__global__ void gn_apply(const float* __restrict__ x,
                         const float* __restrict__ gamma,
                         const float* __restrict__ beta) {
    __shared__ float t[32][33];
    int b  = blockIdx.z;
    int c0 = blockIdx.y * 32;
    int n0 = blockIdx.x * 32;
    #pragma unroll
    for (int i = 0; i < 4; i++) {
        int c = c0 + threadIdx.y + i * 8;
        int n = n0 + threadIdx.x;
        float m = g_mean[b * G_ + c / CG];
        float r = g_rstd[b * G_ + c / CG];
        float v = x[((size_t)(b * C_ + c)) * N_ + n];
        t[threadIdx.y + i * 8][threadIdx.x] = (v - m) * r * gamma[c] + beta[c];
    }
    __syncthreads();
    #pragma unroll
    for (int i = 0; i < 4; i++) {
        int n = n0 + threadIdx.y + i * 8;
        int c = c0 + threadIdx.x;
        g_h[((size_t)(b * N_ + n)) * C_ + c] = t[threadIdx.x][threadIdx.y + i * 8];
    }
}

// ---------------- SGEMM: 128x128 tile, BK=8, 256 threads, 8x8 microtile ----
// Double-buffered SMEM + packed fma.rn.f32x2 inner loop with ZERO pack movs:
//  - A is staged into SMEM pre-duplicated as float2(v,v)  -> LDS.128 yields
//    ready f32x2 broadcast operands
//  - B pairs (b[2p],b[2p+1]) are contiguous in SMEM       -> LDS.128 yields
//    ready f32x2 column-pair operands
// Inner loop per k-step: 6 LDS.128 + 32 FMA2 = 38 issue slots / 64 FMAs.
// C[M,N] = scale * (A[M,K] x Bop) + bias, batched via blockIdx.z
//   NT=true : B is [N,K] row-major (K contiguous)  -> C = A * B^T
//   NT=false: B is [K,N] row-major (N contiguous)  -> C = A * B
template<bool NT, bool HAS_BIAS>
__global__ __launch_bounds__(256, 2) void gemm128(
    const float* __restrict__ A, size_t sA,
    const float* __restrict__ B, size_t sB,
    const float* __restrict__ bias,
    float* __restrict__ C, size_t sC,
    int M, int N, int K, float scale)
{
    __shared__ float2 As[2][8][130];   // duplicated A; row pitch 130*8B (16B-mult)
    __shared__ float  Bs[2][8][132];   // row pitch 132*4B (16B-mult)

    int bz = blockIdx.z;
    A += (size_t)bz * sA;
    B += (size_t)bz * sB;
    C += (size_t)bz * sC;

    const int m0 = blockIdx.y * 128;
    const int n0 = blockIdx.x * 128;
    const int tid = threadIdx.x;
    const int tx = tid & 15, ty = tid >> 4;

    // A-tile loader: row = tid>>1 (0..127), k-quad = (tid&1)*4
    const int arow = tid >> 1;
    const int akq  = (tid & 1) * 4;
    // B NN loader: krow = tid>>5 (0..7), n-quad = (tid&31)*4
    const int bkrow = tid >> 5;
    const int bnq   = (tid & 31) * 4;

    // packed accumulators: acc2[i][p] = (C[i][2p], C[i][2p+1])
    unsigned long long acc2[8][4];
    #pragma unroll
    for (int i = 0; i < 8; i++)
        #pragma unroll
        for (int p = 0; p < 4; p++) acc2[i][p] = 0ull;

    // prologue: load first K-tile into registers
    float4 av = *(const float4*)&A[(size_t)(m0 + arow) * K + akq];
    float4 bv = NT ? *(const float4*)&B[(size_t)(n0 + arow) * K + akq]
                   : *(const float4*)&B[(size_t)bkrow * N + n0 + bnq];

    int buf = 0;
    for (int k0 = 0; k0 < K; k0 += 8) {
        // stage current tile (A duplicated for f32x2 broadcast)
        As[buf][akq + 0][arow] = make_float2(av.x, av.x);
        As[buf][akq + 1][arow] = make_float2(av.y, av.y);
        As[buf][akq + 2][arow] = make_float2(av.z, av.z);
        As[buf][akq + 3][arow] = make_float2(av.w, av.w);
        if (NT) {
            Bs[buf][akq + 0][arow] = bv.x;
            Bs[buf][akq + 1][arow] = bv.y;
            Bs[buf][akq + 2][arow] = bv.z;
            Bs[buf][akq + 3][arow] = bv.w;
        } else {
            *(float4*)&Bs[buf][bkrow][bnq] = bv;
        }
        __syncthreads();

        // issue next tile's global loads (latency hidden by compute below)
        if (k0 + 8 < K) {
            av = *(const float4*)&A[(size_t)(m0 + arow) * K + k0 + 8 + akq];
            bv = NT ? *(const float4*)&B[(size_t)(n0 + arow) * K + k0 + 8 + akq]
                    : *(const float4*)&B[(size_t)(k0 + 8 + bkrow) * N + n0 + bnq];
        }

        #pragma unroll
        for (int k = 0; k < 8; k++) {
            // A fragment: 8 duplicated f32x2 via 4x LDS.128 (broadcast per warp)
            ulonglong2 a01 = *(const ulonglong2*)&As[buf][k][ty * 8 + 0];
            ulonglong2 a23 = *(const ulonglong2*)&As[buf][k][ty * 8 + 2];
            ulonglong2 a45 = *(const ulonglong2*)&As[buf][k][ty * 8 + 4];
            ulonglong2 a67 = *(const ulonglong2*)&As[buf][k][ty * 8 + 6];
            // B fragment: 4 column-pair f32x2 via 2x LDS.128
            ulonglong2 b01 = *(const ulonglong2*)&Bs[buf][k][tx * 8 + 0];
            ulonglong2 b23 = *(const ulonglong2*)&Bs[buf][k][tx * 8 + 4];

            unsigned long long ap[8] = { a01.x, a01.y, a23.x, a23.y,
                                         a45.x, a45.y, a67.x, a67.y };
            unsigned long long bp[4] = { b01.x, b01.y, b23.x, b23.y };

            #pragma unroll
            for (int i = 0; i < 8; i++)
                #pragma unroll
                for (int p = 0; p < 4; p++)
                    FMA_F32X2(acc2[i][p], ap[i], bp[p], acc2[i][p]);
        }
        buf ^= 1;
    }

    float bvals[8];
    if (HAS_BIAS) {
        #pragma unroll
        for (int j = 0; j < 8; j++) bvals[j] = bias[n0 + tx * 8 + j];
    }
    #pragma unroll
    for (int i = 0; i < 8; i++) {
        float c[8];
        #pragma unroll
        for (int p = 0; p < 4; p++) UNPACK_F32X2(c[2 * p], c[2 * p + 1], acc2[i][p]);
        size_t off = (size_t)(m0 + ty * 8 + i) * N + n0 + tx * 8;
        float4 r0, r1;
        r0.x = c[0] * scale + (HAS_BIAS ? bvals[0] : 0.f);
        r0.y = c[1] * scale + (HAS_BIAS ? bvals[1] : 0.f);
        r0.z = c[2] * scale + (HAS_BIAS ? bvals[2] : 0.f);
        r0.w = c[3] * scale + (HAS_BIAS ? bvals[3] : 0.f);
        r1.x = c[4] * scale + (HAS_BIAS ? bvals[4] : 0.f);
        r1.y = c[5] * scale + (HAS_BIAS ? bvals[5] : 0.f);
        r1.z = c[6] * scale + (HAS_BIAS ? bvals[6] : 0.f);
        r1.w = c[7] * scale + (HAS_BIAS ? bvals[7] : 0.f);
        *(float4*)&C[off]     = r0;
        *(float4*)&C[off + 4] = r1;
    }
}

// ---------------- row softmax over 1024 elements, one block/row ------------
__global__ void softmax1024(float* __restrict__ s) {
    float4* p = (float4*)(s + (size_t)blockIdx.x * N_);
    const int tid = threadIdx.x;          // 256 threads, one float4 each
    const int w = tid >> 5, l = tid & 31;
    __shared__ float red[8];

    float4 v = p[tid];
    float mx = fmaxf(fmaxf(v.x, v.y), fmaxf(v.z, v.w));
    #pragma unroll
    for (int o = 16; o; o >>= 1) mx = fmaxf(mx, __shfl_xor_sync(0xffffffffu, mx, o));
    if (l == 0) red[w] = mx;
    __syncthreads();
    mx = red[0];
    #pragma unroll
    for (int i = 1; i < 8; i++) mx = fmaxf(mx, red[i]);
    __syncthreads();

    v.x = __expf(v.x - mx);
    v.y = __expf(v.y - mx);
    v.z = __expf(v.z - mx);
    v.w = __expf(v.w - mx);
    float sum = v.x + v.y + v.z + v.w;
    #pragma unroll
    for (int o = 16; o; o >>= 1) sum += __shfl_xor_sync(0xffffffffu, sum, o);
    if (l == 0) red[w] = sum;
    __syncthreads();
    sum = red[0] + red[1] + red[2] + red[3] + red[4] + red[5] + red[6] + red[7];

    float inv = 1.0f / sum;
    v.x *= inv; v.y *= inv; v.z *= inv; v.w *= inv;
    p[tid] = v;
}

// ---------------- transpose [B,N,C] -> [B,C,N] + residual add --------------
__global__ void add_tr(const float* __restrict__ o,
                       const float* __restrict__ x,
                       float* __restrict__ out) {
    __shared__ float t[32][33];
    int b  = blockIdx.z;
    int c0 = blockIdx.y * 32;
    int n0 = blockIdx.x * 32;
    #pragma unroll
    for (int i = 0; i < 4; i++) {
        int n = n0 + threadIdx.y + i * 8;
        int c = c0 + threadIdx.x;
        t[threadIdx.y + i * 8][threadIdx.x] = o[((size_t)(b * N_ + n)) * C_ + c];
    }
    __syncthreads();
    #pragma unroll
    for (int i = 0; i < 4; i++) {
        int c = c0 + threadIdx.y + i * 8;
        int n = n0 + threadIdx.x;
        size_t idx = ((size_t)(b * C_ + c)) * N_ + n;
        out[idx] = t[threadIdx.x][threadIdx.y + i * 8] + x[idx];
    }
}

// ---------------- launch ----------------
extern "C" void kernel_launch(void* const* d_in, const int* in_sizes, int n_in,
                              void* d_out, int out_size) {
    (void)in_sizes; (void)n_in; (void)out_size;
    const float* x     = (const float*)d_in[0];
    const float* Wq    = (const float*)d_in[1];
    const float* bq    = (const float*)d_in[2];
    const float* Wk    = (const float*)d_in[3];
    const float* bk    = (const float*)d_in[4];
    const float* Wv    = (const float*)d_in[5];
    const float* bv    = (const float*)d_in[6];
    const float* gamma = (const float*)d_in[7];
    const float* beta  = (const float*)d_in[8];
    float* out = (float*)d_out;

    float *h, *q, *kb, *vb, *s;
    cudaGetSymbolAddress((void**)&h,  g_h);
    cudaGetSymbolAddress((void**)&q,  g_q);
    cudaGetSymbolAddress((void**)&kb, g_k);
    cudaGetSymbolAddress((void**)&vb, g_v);
    cudaGetSymbolAddress((void**)&s,  g_s);

    const size_t sHC = (size_t)N_ * C_;     // per-batch stride of [N,C] buffers
    const size_t sNN = (size_t)N_ * N_;     // per-batch stride of scores

    gn_stats<<<B_ * G_, 512>>>(x);
    gn_apply<<<dim3(N_ / 32, C_ / 32, B_), dim3(32, 8)>>>(x, gamma, beta);

    // QKV projections: [1024,256] = h[1024,256] * W^T + b   (NT, with bias)
    dim3 gqkv(C_ / 128, N_ / 128, B_);
    gemm128<true,  true ><<<gqkv, 256>>>(h, sHC, Wq, 0, bq, q,  sHC, N_, C_, C_, 1.0f);
    gemm128<true,  true ><<<gqkv, 256>>>(h, sHC, Wk, 0, bk, kb, sHC, N_, C_, C_, 1.0f);
    gemm128<true,  true ><<<gqkv, 256>>>(h, sHC, Wv, 0, bv, vb, sHC, N_, C_, C_, 1.0f);

    // scores = q * k^T / sqrt(C)   (NT, scale folded into epilogue)
    dim3 gsc(N_ / 128, N_ / 128, B_);
    gemm128<true,  false><<<gsc, 256>>>(q, sHC, kb, sHC, nullptr, s, sNN, N_, N_, C_, 1.0f / 16.0f);

    softmax1024<<<B_ * N_, 256>>>(s);

    // out_attn = attn * v   (NN) — reuse g_h as output buffer
    dim3 gav(C_ / 128, N_ / 128, B_);
    gemm128<false, false><<<gav, 256>>>(s, sNN, vb, sHC, nullptr, h, sHC, N_, C_, N_, 1.0f);

    add_tr<<<dim3(N_ / 32, C_ / 32, B_), dim3(32, 8)>>>(h, x, out);
}

// round 6
// speedup vs baseline: 2.8765x; 2.8765x over previous
#include <cuda_runtime.h>
#include <math.h>

#define B_  16
#define C_  256
#define N_  1024
#define G_  4
#define CG  64          // channels per group

// ---------------- scratch (static device memory; no allocs) ----------------
__device__ float g_h[B_ * N_ * C_];        // normalized activations [B,N,C], later reused for attn output
__device__ float g_q[B_ * N_ * C_];
__device__ float g_k[B_ * N_ * C_];
__device__ float g_v[B_ * N_ * C_];
__device__ float g_s[B_ * N_ * N_];        // scores / attn [B,N,N]  (67 MB)
__device__ float g_mean[B_ * G_];
__device__ float g_rstd[B_ * G_];

// ---------------- tf32 mma helpers ----------------
__device__ __forceinline__ unsigned f2tf32(float f) {
    unsigned r;
    asm("cvt.rna.tf32.f32 %0, %1;" : "=r"(r) : "f"(f));
    return r;
}

// D += A(16x8) * B(8x8), tf32 inputs, fp32 accum
__device__ __forceinline__ void mma_tf32(float* d, const unsigned* a, const unsigned* b) {
    asm volatile(
        "mma.sync.aligned.m16n8k8.row.col.f32.tf32.tf32.f32 "
        "{%0,%1,%2,%3}, {%4,%5,%6,%7}, {%8,%9}, {%0,%1,%2,%3};"
        : "+f"(d[0]), "+f"(d[1]), "+f"(d[2]), "+f"(d[3])
        : "r"(a[0]), "r"(a[1]), "r"(a[2]), "r"(a[3]), "r"(b[0]), "r"(b[1]));
}

// ---------------- GroupNorm stats: one block per (b,g) ----------------
__global__ void gn_stats(const float* __restrict__ x) {
    int bg = blockIdx.x;                           // 0..63
    const float4* xp4 = (const float4*)(x + (size_t)bg * (CG * N_));
    float s = 0.f, ss = 0.f;
    const int n4 = (CG * N_) / 4;                  // 16384 float4
    for (int i = threadIdx.x; i < n4; i += blockDim.x) {
        float4 v = xp4[i];
        s  += v.x + v.y + v.z + v.w;
        ss += v.x * v.x + v.y * v.y + v.z * v.z + v.w * v.w;
    }
    __shared__ float rs[16], rss[16];
    #pragma unroll
    for (int o = 16; o; o >>= 1) {
        s  += __shfl_down_sync(0xffffffffu, s, o);
        ss += __shfl_down_sync(0xffffffffu, ss, o);
    }
    int w = threadIdx.x >> 5, l = threadIdx.x & 31;
    if (l == 0) { rs[w] = s; rss[w] = ss; }
    __syncthreads();
    if (w == 0) {
        int nw = blockDim.x >> 5;
        s  = (l < nw) ? rs[l]  : 0.f;
        ss = (l < nw) ? rss[l] : 0.f;
        #pragma unroll
        for (int o = 16; o; o >>= 1) {
            s  += __shfl_down_sync(0xffffffffu, s, o);
            ss += __shfl_down_sync(0xffffffffu, ss, o);
        }
        if (l == 0) {
            const float inv_n = 1.0f / (CG * N_);
            float m   = s * inv_n;
            float var = ss * inv_n - m * m;
            g_mean[bg] = m;
            g_rstd[bg] = rsqrtf(var + 1e-5f);
        }
    }
}

// ---------------- normalize + transpose [B,C,N] -> h[B,N,C] ----------------
__global__ void gn_apply(const float* __restrict__ x,
                         const float* __restrict__ gamma,
                         const float* __restrict__ beta) {
    __shared__ float t[32][33];
    int b  = blockIdx.z;
    int c0 = blockIdx.y * 32;
    int n0 = blockIdx.x * 32;
    #pragma unroll
    for (int i = 0; i < 4; i++) {
        int c = c0 + threadIdx.y + i * 8;
        int n = n0 + threadIdx.x;
        float m = g_mean[b * G_ + c / CG];
        float r = g_rstd[b * G_ + c / CG];
        float v = x[((size_t)(b * C_ + c)) * N_ + n];
        t[threadIdx.y + i * 8][threadIdx.x] = (v - m) * r * gamma[c] + beta[c];
    }
    __syncthreads();
    #pragma unroll
    for (int i = 0; i < 4; i++) {
        int n = n0 + threadIdx.y + i * 8;
        int c = c0 + threadIdx.x;
        g_h[((size_t)(b * N_ + n)) * C_ + c] = t[threadIdx.x][threadIdx.y + i * 8];
    }
}

// ---------------- tf32 tensor-core GEMM ----------------
// 128x128 CTA tile, BK=16 (2x k8 mma steps), 256 threads = 8 warps,
// warp tile 64(m) x 32(n) = 4 m16-tiles x 4 n8-tiles, fp32 accumulators.
// Operands staged into SMEM FRAGMENT-MAJOR (scattered at STS, cvt to tf32),
// so the mainloop reads A-fragments with LDS.128 and B-fragments with LDS.64,
// both conflict-free. Double-buffered with register prefetch.
// C[M,N] = scale * (A[M,K] x Bop) + bias, batched via blockIdx.z
//   NT=true : B is [N,K] row-major (K contiguous)  -> C = A * B^T
//   NT=false: B is [K,N] row-major (N contiguous)  -> C = A * B
template<bool NT, bool HAS_BIAS>
__global__ __launch_bounds__(256, 2) void gemm_tc(
    const float* __restrict__ A, size_t sA,
    const float* __restrict__ B, size_t sB,
    const float* __restrict__ bias,
    float* __restrict__ C, size_t sC,
    int M, int N, int K, float scale)
{
    // [buf][k8][tile][lane][reg]
    __shared__ __align__(16) unsigned As[2][2][8][32][4];   // 16 KB
    __shared__ __align__(16) unsigned Bs[2][2][16][32][2];  // 16 KB

    int bz = blockIdx.z;
    A += (size_t)bz * sA;
    B += (size_t)bz * sB;
    C += (size_t)bz * sC;

    const int m0 = blockIdx.y * 128;
    const int n0 = blockIdx.x * 128;
    const int tid = threadIdx.x;
    const int lane = tid & 31, w = tid >> 5;
    const int wm = (w & 1) * 4;      // first m16-tile of this warp
    const int wn = (w >> 1) * 4;     // first n8-tile of this warp

    // A loader: row = tid>>1 (0..127), k-half = (tid&1)*8
    const int arow = tid >> 1;
    const int acol = (tid & 1) * 8;
    // B NT loader: same shape as A (row = n, k-half)
    // B NN loader: k-row = tid>>4 (0..15), n-chunk = (tid&15)*8
    const int bkr = tid >> 4;
    const int bnc = (tid & 15) * 8;

    // precomputed scatter constants
    const int a_mt = arow >> 4, a_g4 = (arow & 7) * 4, a_hm = (arow >> 3) & 1;
    const int a_k8 = acol >> 3;
    const int bt_nt = arow >> 3, bt_g4 = (arow & 7) * 4;   // NT: n = arow
    const int bt_k8 = acol >> 3;
    const int bn_k8 = bkr >> 3, bn_t = bkr & 3, bn_hk = (bkr >> 2) & 1;
    const int bn_nt = bnc >> 3;

    float d[4][4][4] = {};  // [m16][n8][reg]

    // prologue: load slab 0
    float4 av0 = *(const float4*)&A[(size_t)(m0 + arow) * K + acol];
    float4 av1 = *(const float4*)&A[(size_t)(m0 + arow) * K + acol + 4];
    float4 bv0, bv1;
    if (NT) {
        bv0 = *(const float4*)&B[(size_t)(n0 + arow) * K + acol];
        bv1 = *(const float4*)&B[(size_t)(n0 + arow) * K + acol + 4];
    } else {
        bv0 = *(const float4*)&B[(size_t)bkr * N + n0 + bnc];
        bv1 = *(const float4*)&B[(size_t)bkr * N + n0 + bnc + 4];
    }

    int buf = 0;
    for (int k0 = 0; k0 < K; k0 += 16) {
        // ---- scatter current slab into fragment-major SMEM ----
        {
            float avv[8] = { av0.x, av0.y, av0.z, av0.w, av1.x, av1.y, av1.z, av1.w };
            #pragma unroll
            for (int i = 0; i < 8; i++)
                As[buf][a_k8][a_mt][a_g4 + (i & 3)][(i >> 2) * 2 + a_hm] = f2tf32(avv[i]);

            float bvv[8] = { bv0.x, bv0.y, bv0.z, bv0.w, bv1.x, bv1.y, bv1.z, bv1.w };
            if (NT) {
                #pragma unroll
                for (int i = 0; i < 8; i++)
                    Bs[buf][bt_k8][bt_nt][bt_g4 + (i & 3)][i >> 2] = f2tf32(bvv[i]);
            } else {
                #pragma unroll
                for (int i = 0; i < 8; i++)
                    Bs[buf][bn_k8][bn_nt][i * 4 + bn_t][bn_hk] = f2tf32(bvv[i]);
            }
        }
        __syncthreads();

        // ---- prefetch next slab (latency hidden under mma) ----
        if (k0 + 16 < K) {
            av0 = *(const float4*)&A[(size_t)(m0 + arow) * K + k0 + 16 + acol];
            av1 = *(const float4*)&A[(size_t)(m0 + arow) * K + k0 + 16 + acol + 4];
            if (NT) {
                bv0 = *(const float4*)&B[(size_t)(n0 + arow) * K + k0 + 16 + acol];
                bv1 = *(const float4*)&B[(size_t)(n0 + arow) * K + k0 + 16 + acol + 4];
            } else {
                bv0 = *(const float4*)&B[(size_t)(k0 + 16 + bkr) * N + n0 + bnc];
                bv1 = *(const float4*)&B[(size_t)(k0 + 16 + bkr) * N + n0 + bnc + 4];
            }
        }

        // ---- compute 2 k8-steps ----
        #pragma unroll
        for (int k8 = 0; k8 < 2; k8++) {
            unsigned a[4][4], b[4][2];
            #pragma unroll
            for (int i = 0; i < 4; i++)
                *(uint4*)&a[i][0] = *(const uint4*)&As[buf][k8][wm + i][lane][0];
            #pragma unroll
            for (int j = 0; j < 4; j++)
                *(uint2*)&b[j][0] = *(const uint2*)&Bs[buf][k8][wn + j][lane][0];
            #pragma unroll
            for (int i = 0; i < 4; i++)
                #pragma unroll
                for (int j = 0; j < 4; j++)
                    mma_tf32(d[i][j], a[i], b[j]);
        }
        buf ^= 1;
    }

    // ---- epilogue: scale + bias, write fp32 ----
    const int g = lane >> 2, t = lane & 3;
    #pragma unroll
    for (int j = 0; j < 4; j++) {
        int c0i = n0 + (wn + j) * 8 + t * 2;
        float bvx = 0.f, bvy = 0.f;
        if (HAS_BIAS) { bvx = bias[c0i]; bvy = bias[c0i + 1]; }
        #pragma unroll
        for (int i = 0; i < 4; i++) {
            int r0 = m0 + (wm + i) * 16 + g;
            float2 lo = make_float2(d[i][j][0] * scale + bvx, d[i][j][1] * scale + bvy);
            float2 hi = make_float2(d[i][j][2] * scale + bvx, d[i][j][3] * scale + bvy);
            *(float2*)&C[(size_t)r0 * N + c0i]       = lo;
            *(float2*)&C[(size_t)(r0 + 8) * N + c0i] = hi;
        }
    }
}

// ---------------- row softmax over 1024 elements, one block/row ------------
__global__ void softmax1024(float* __restrict__ s) {
    float4* p = (float4*)(s + (size_t)blockIdx.x * N_);
    const int tid = threadIdx.x;          // 256 threads, one float4 each
    const int w = tid >> 5, l = tid & 31;
    __shared__ float red[8];

    float4 v = p[tid];
    float mx = fmaxf(fmaxf(v.x, v.y), fmaxf(v.z, v.w));
    #pragma unroll
    for (int o = 16; o; o >>= 1) mx = fmaxf(mx, __shfl_xor_sync(0xffffffffu, mx, o));
    if (l == 0) red[w] = mx;
    __syncthreads();
    mx = red[0];
    #pragma unroll
    for (int i = 1; i < 8; i++) mx = fmaxf(mx, red[i]);
    __syncthreads();

    v.x = __expf(v.x - mx);
    v.y = __expf(v.y - mx);
    v.z = __expf(v.z - mx);
    v.w = __expf(v.w - mx);
    float sum = v.x + v.y + v.z + v.w;
    #pragma unroll
    for (int o = 16; o; o >>= 1) sum += __shfl_xor_sync(0xffffffffu, sum, o);
    if (l == 0) red[w] = sum;
    __syncthreads();
    sum = red[0] + red[1] + red[2] + red[3] + red[4] + red[5] + red[6] + red[7];

    float inv = 1.0f / sum;
    v.x *= inv; v.y *= inv; v.z *= inv; v.w *= inv;
    p[tid] = v;
}

// ---------------- transpose [B,N,C] -> [B,C,N] + residual add --------------
__global__ void add_tr(const float* __restrict__ o,
                       const float* __restrict__ x,
                       float* __restrict__ out) {
    __shared__ float t[32][33];
    int b  = blockIdx.z;
    int c0 = blockIdx.y * 32;
    int n0 = blockIdx.x * 32;
    #pragma unroll
    for (int i = 0; i < 4; i++) {
        int n = n0 + threadIdx.y + i * 8;
        int c = c0 + threadIdx.x;
        t[threadIdx.y + i * 8][threadIdx.x] = o[((size_t)(b * N_ + n)) * C_ + c];
    }
    __syncthreads();
    #pragma unroll
    for (int i = 0; i < 4; i++) {
        int c = c0 + threadIdx.y + i * 8;
        int n = n0 + threadIdx.x;
        size_t idx = ((size_t)(b * C_ + c)) * N_ + n;
        out[idx] = t[threadIdx.x][threadIdx.y + i * 8] + x[idx];
    }
}

// ---------------- launch ----------------
extern "C" void kernel_launch(void* const* d_in, const int* in_sizes, int n_in,
                              void* d_out, int out_size) {
    (void)in_sizes; (void)n_in; (void)out_size;
    const float* x     = (const float*)d_in[0];
    const float* Wq    = (const float*)d_in[1];
    const float* bq    = (const float*)d_in[2];
    const float* Wk    = (const float*)d_in[3];
    const float* bk    = (const float*)d_in[4];
    const float* Wv    = (const float*)d_in[5];
    const float* bv    = (const float*)d_in[6];
    const float* gamma = (const float*)d_in[7];
    const float* beta  = (const float*)d_in[8];
    float* out = (float*)d_out;

    float *h, *q, *kb, *vb, *s;
    cudaGetSymbolAddress((void**)&h,  g_h);
    cudaGetSymbolAddress((void**)&q,  g_q);
    cudaGetSymbolAddress((void**)&kb, g_k);
    cudaGetSymbolAddress((void**)&vb, g_v);
    cudaGetSymbolAddress((void**)&s,  g_s);

    const size_t sHC = (size_t)N_ * C_;     // per-batch stride of [N,C] buffers
    const size_t sNN = (size_t)N_ * N_;     // per-batch stride of scores

    gn_stats<<<B_ * G_, 512>>>(x);
    gn_apply<<<dim3(N_ / 32, C_ / 32, B_), dim3(32, 8)>>>(x, gamma, beta);

    // QKV projections: [1024,256] = h[1024,256] * W^T + b   (NT, with bias)
    dim3 gqkv(C_ / 128, N_ / 128, B_);
    gemm_tc<true,  true ><<<gqkv, 256>>>(h, sHC, Wq, 0, bq, q,  sHC, N_, C_, C_, 1.0f);
    gemm_tc<true,  true ><<<gqkv, 256>>>(h, sHC, Wk, 0, bk, kb, sHC, N_, C_, C_, 1.0f);
    gemm_tc<true,  true ><<<gqkv, 256>>>(h, sHC, Wv, 0, bv, vb, sHC, N_, C_, C_, 1.0f);

    // scores = q * k^T / sqrt(C)   (NT, scale folded into epilogue)
    dim3 gsc(N_ / 128, N_ / 128, B_);
    gemm_tc<true,  false><<<gsc, 256>>>(q, sHC, kb, sHC, nullptr, s, sNN, N_, N_, C_, 1.0f / 16.0f);

    softmax1024<<<B_ * N_, 256>>>(s);

    // out_attn = attn * v   (NN) — reuse g_h as output buffer
    dim3 gav(C_ / 128, N_ / 128, B_);
    gemm_tc<false, false><<<gav, 256>>>(s, sNN, vb, sHC, nullptr, h, sHC, N_, C_, N_, 1.0f);

    add_tr<<<dim3(N_ / 32, C_ / 32, B_), dim3(32, 8)>>>(h, x, out);
}